// round 7
// baseline (speedup 1.0000x reference)
#include <cuda_runtime.h>

// EMA over x[32, 4096, 256] fp32, adjust=True, period=25.
// Round-7: identical to round-6 (best: scalar lanes, 8 chunks of 512,
// warmup 192 from e=0, depth-3 pipeline / 48 LDGs in flight per warp,
// 2048 warps in 64-thread blocks) with ONE change: all output stores are
// __stcs (evict-first streaming). Output is never re-read; keeping it out
// of L2 preserves residency for input lines (warmup reuse) and cleans up
// the LTS read/write interleave.

#define B_DIM   32
#define T_DIM   4096
#define F_DIM   256
#define CHUNK   512
#define NCHUNK  8
#define WARMUP  192
#define UB      16
#define NB_MAIN ((WARMUP + CHUNK) / UB)   // 44
#define NB_ZERO (CHUNK / UB)              // 32
#define WARM_B  (WARMUP / UB)             // 12

#define ALPHA_C (2.0f / 26.0f)
#define OMA_C   (1.0f - ALPHA_C)

__device__ __forceinline__ void load_batch(float (&d)[UB],
                                           const float* __restrict__ p) {
#pragma unroll
    for (int i = 0; i < UB; i++)
        d[i] = __ldg(p + (size_t)i * F_DIM);
}

// Constant-coefficient batch (w_t == 1.0f exactly for t >= 207).
__device__ __forceinline__ void proc_const(const float (&xv)[UB], float& e,
                                           float* __restrict__ po, bool st) {
#pragma unroll
    for (int i = 0; i < UB; i++) {
        e = fmaf(OMA_C, e, ALPHA_C * xv[i]);
        if (st) __stcs(po + (size_t)i * F_DIM, e);
    }
}

// Exact adjusted recurrence; p0 = oma^{t0} on entry. Reciprocals off-chain.
__device__ __forceinline__ void proc_adj(const float (&xv)[UB], float& e,
                                         float& p0, float* __restrict__ po) {
    float rw[UB];
    float q = 1.0f;
#pragma unroll
    for (int i = 0; i < UB; i++) {
        q *= OMA_C;                    // compile-time powers
        float wt = 1.0f - p0 * q;      // >= alpha, never degenerate
        rw[i] = __fdividef(1.0f, wt);
    }
    p0 *= q;
#pragma unroll
    for (int i = 0; i < UB; i++) {
        e = fmaf(OMA_C * rw[i], e, (ALPHA_C * rw[i]) * xv[i]);
        __stcs(po + (size_t)i * F_DIM, e);
    }
}

__global__ void __launch_bounds__(64)
ema_stcs_kernel(const float* __restrict__ x, float* __restrict__ out) {
    int g     = blockIdx.x * 64 + threadIdx.x;
    int lane  = g & 31;
    int w     = g >> 5;                 // warp id 0..2047
    int f_hi  = w & 7;
    int chunk = (w >> 3) & (NCHUNK - 1);
    int b     = w >> 6;
    int f     = f_hi * 32 + lane;

    size_t seq_base = ((size_t)b * T_DIM) * F_DIM + f;
    const size_t STRIDE = (size_t)UB * F_DIM;
    float* __restrict__ po = out + seq_base + (size_t)chunk * CHUNK * F_DIM;

    float e = 0.0f;
    float bA[UB], bB[UB], bC[UB], bD[UB];

    if (chunk == 0) {
        // 512 exact-adjusted steps from t=0 (e_{-1}=0 gives e_0 = x_0).
        const float* __restrict__ px = x + seq_base;
        float p0 = 1.0f;
        load_batch(bA, px); px += STRIDE;
        load_batch(bB, px); px += STRIDE;
        load_batch(bC, px); px += STRIDE;
#pragma unroll 1
        for (int bt = 0; bt < NB_ZERO; bt += 4) {
            if (bt + 3 < NB_ZERO) { load_batch(bD, px); px += STRIDE; }
            proc_adj(bA, e, p0, po); po += STRIDE;
            if (bt + 4 < NB_ZERO) { load_batch(bA, px); px += STRIDE; }
            proc_adj(bB, e, p0, po); po += STRIDE;
            if (bt + 5 < NB_ZERO) { load_batch(bB, px); px += STRIDE; }
            proc_adj(bC, e, p0, po); po += STRIDE;
            if (bt + 6 < NB_ZERO) { load_batch(bC, px); px += STRIDE; }
            proc_adj(bD, e, p0, po); po += STRIDE;
        }
    } else {
        // 192 warmup steps (no store) + 512 constant-coefficient steps.
        const float* __restrict__ px =
            x + seq_base + ((size_t)chunk * CHUNK - WARMUP) * F_DIM;
        load_batch(bA, px); px += STRIDE;
        load_batch(bB, px); px += STRIDE;
        load_batch(bC, px); px += STRIDE;
#pragma unroll 1
        for (int bt = 0; bt < NB_MAIN; bt += 4) {
            bool s0 = (bt     >= WARM_B);
            bool s1 = (bt + 1 >= WARM_B);
            bool s2 = (bt + 2 >= WARM_B);
            bool s3 = (bt + 3 >= WARM_B);
            if (bt + 3 < NB_MAIN) { load_batch(bD, px); px += STRIDE; }
            proc_const(bA, e, po, s0); if (s0) po += STRIDE;
            if (bt + 4 < NB_MAIN) { load_batch(bA, px); px += STRIDE; }
            proc_const(bB, e, po, s1); if (s1) po += STRIDE;
            if (bt + 5 < NB_MAIN) { load_batch(bB, px); px += STRIDE; }
            proc_const(bC, e, po, s2); if (s2) po += STRIDE;
            if (bt + 6 < NB_MAIN) { load_batch(bC, px); px += STRIDE; }
            proc_const(bD, e, po, s3); if (s3) po += STRIDE;
        }
    }
}

extern "C" void kernel_launch(void* const* d_in, const int* in_sizes, int n_in,
                              void* d_out, int out_size) {
    const float* x = (const float*)d_in[0];
    float* out = (float*)d_out;
    // 2048 warps, 2 per block -> 1024 blocks
    ema_stcs_kernel<<<1024, 64>>>(x, out);
}

// round 8
// speedup vs baseline: 1.0634x; 1.0634x over previous
#include <cuda_runtime.h>

// EMA over x[32, 4096, 256] fp32, adjust=True, period=25.
// Round-8: round-6 mainloop (best: scalar lanes, 8 chunks of 512, warmup 192
// from e=0, depth-3 pipeline = 48 LDGs in flight/warp, normal STG stores —
// __stcs was a confirmed regression) with ONE structural change:
// 256-thread blocks grouping all 8 f-group warps of one (b, chunk).
// Each timestep's 1KB DRAM row (256 feats x 4B) is now read/written by
// co-resident, near-lockstep warps -> clustered row hits at the memory
// controller instead of 8 x 128B scattered across 4 SMs.

#define B_DIM   32
#define T_DIM   4096
#define F_DIM   256
#define CHUNK   512
#define NCHUNK  8
#define WARMUP  192
#define UB      16
#define NB_MAIN ((WARMUP + CHUNK) / UB)   // 44
#define NB_ZERO (CHUNK / UB)              // 32
#define WARM_B  (WARMUP / UB)             // 12

#define ALPHA_C (2.0f / 26.0f)
#define OMA_C   (1.0f - ALPHA_C)

__device__ __forceinline__ void load_batch(float (&d)[UB],
                                           const float* __restrict__ p) {
#pragma unroll
    for (int i = 0; i < UB; i++)
        d[i] = __ldg(p + (size_t)i * F_DIM);
}

// Constant-coefficient batch (w_t == 1.0f exactly for t >= 207).
__device__ __forceinline__ void proc_const(const float (&xv)[UB], float& e,
                                           float* __restrict__ po, bool st) {
#pragma unroll
    for (int i = 0; i < UB; i++) {
        e = fmaf(OMA_C, e, ALPHA_C * xv[i]);
        if (st) po[(size_t)i * F_DIM] = e;
    }
}

// Exact adjusted recurrence; p0 = oma^{t0} on entry. Reciprocals off-chain.
__device__ __forceinline__ void proc_adj(const float (&xv)[UB], float& e,
                                         float& p0, float* __restrict__ po) {
    float rw[UB];
    float q = 1.0f;
#pragma unroll
    for (int i = 0; i < UB; i++) {
        q *= OMA_C;                    // compile-time powers
        float wt = 1.0f - p0 * q;      // >= alpha, never degenerate
        rw[i] = __fdividef(1.0f, wt);
    }
    p0 *= q;
#pragma unroll
    for (int i = 0; i < UB; i++) {
        e = fmaf(OMA_C * rw[i], e, (ALPHA_C * rw[i]) * xv[i]);
        po[(size_t)i * F_DIM] = e;
    }
}

__global__ void __launch_bounds__(256)
ema_row_kernel(const float* __restrict__ x, float* __restrict__ out) {
    int lane  = threadIdx.x & 31;
    int f_hi  = threadIdx.x >> 5;        // warp in block = f-group 0..7
    int blk   = blockIdx.x;              // 0..255 = (b, chunk)
    int chunk = blk & (NCHUNK - 1);
    int b     = blk >> 3;                // 0..31
    int f     = f_hi * 32 + lane;        // full 1KB row covered per block

    size_t seq_base = ((size_t)b * T_DIM) * F_DIM + f;
    const size_t STRIDE = (size_t)UB * F_DIM;
    float* __restrict__ po = out + seq_base + (size_t)chunk * CHUNK * F_DIM;

    float e = 0.0f;
    float bA[UB], bB[UB], bC[UB], bD[UB];

    if (chunk == 0) {
        // 512 exact-adjusted steps from t=0 (e_{-1}=0 gives e_0 = x_0).
        const float* __restrict__ px = x + seq_base;
        float p0 = 1.0f;
        load_batch(bA, px); px += STRIDE;
        load_batch(bB, px); px += STRIDE;
        load_batch(bC, px); px += STRIDE;
#pragma unroll 1
        for (int bt = 0; bt < NB_ZERO; bt += 4) {
            if (bt + 3 < NB_ZERO) { load_batch(bD, px); px += STRIDE; }
            proc_adj(bA, e, p0, po); po += STRIDE;
            if (bt + 4 < NB_ZERO) { load_batch(bA, px); px += STRIDE; }
            proc_adj(bB, e, p0, po); po += STRIDE;
            if (bt + 5 < NB_ZERO) { load_batch(bB, px); px += STRIDE; }
            proc_adj(bC, e, p0, po); po += STRIDE;
            if (bt + 6 < NB_ZERO) { load_batch(bC, px); px += STRIDE; }
            proc_adj(bD, e, p0, po); po += STRIDE;
        }
    } else {
        // 192 warmup steps (no store) + 512 constant-coefficient steps.
        const float* __restrict__ px =
            x + seq_base + ((size_t)chunk * CHUNK - WARMUP) * F_DIM;
        load_batch(bA, px); px += STRIDE;
        load_batch(bB, px); px += STRIDE;
        load_batch(bC, px); px += STRIDE;
#pragma unroll 1
        for (int bt = 0; bt < NB_MAIN; bt += 4) {
            bool s0 = (bt     >= WARM_B);
            bool s1 = (bt + 1 >= WARM_B);
            bool s2 = (bt + 2 >= WARM_B);
            bool s3 = (bt + 3 >= WARM_B);
            if (bt + 3 < NB_MAIN) { load_batch(bD, px); px += STRIDE; }
            proc_const(bA, e, po, s0); if (s0) po += STRIDE;
            if (bt + 4 < NB_MAIN) { load_batch(bA, px); px += STRIDE; }
            proc_const(bB, e, po, s1); if (s1) po += STRIDE;
            if (bt + 5 < NB_MAIN) { load_batch(bB, px); px += STRIDE; }
            proc_const(bC, e, po, s2); if (s2) po += STRIDE;
            if (bt + 6 < NB_MAIN) { load_batch(bC, px); px += STRIDE; }
            proc_const(bD, e, po, s3); if (s3) po += STRIDE;
        }
    }
}

extern "C" void kernel_launch(void* const* d_in, const int* in_sizes, int n_in,
                              void* d_out, int out_size) {
    const float* x = (const float*)d_in[0];
    float* out = (float*)d_out;
    // 256 blocks x 8 warps: one block per (b, chunk), covering full 1KB rows
    ema_row_kernel<<<B_DIM * NCHUNK, 256>>>(x, out);
}